// round 13
// baseline (speedup 1.0000x reference)
#include <cuda_runtime.h>
#include <stdint.h>

// Problem constants: B=16, L=4096, H=768 (fp32)
#define B_ 16
#define L_ 4096
#define H_ 768
#define H4 (H_ / 4)            // 192 float4 lanes per row
#define TOK_PER_BLK 16         // tokens per tile
#define SROWS 4                // rows per pipeline stage (12 KB)
#define NSTAGES 3              // pipeline depth (36 KB smem)
#define NCWARPS 6              // consumer warps (192 lanes)
#define NTHREADS 224           // 6 consumer warps + 1 producer warp
#define TILES_PER_BATCH (L_ / TOK_PER_BLK)   // 256
#define NUM_TILES (B_ * TILES_PER_BATCH)     // 4096
#define GRID_BLOCKS (148 * 6)                // 888: one residency wave
#define MAX_TILES_PER_CTA ((NUM_TILES + GRID_BLOCKS - 1) / GRID_BLOCKS)  // 5

// Precomputed lower bounds: bnd_g[b][v] = first p with seg[b][p] >= v, v in [0,L]
__device__ int bnd_g[B_ * (L_ + 1)];

// Kernel 1: linear-pass boundary computation (seg sorted per batch row).
__global__ __launch_bounds__(256)
void bounds_kernel(const int* __restrict__ seg)
{
    const int b = blockIdx.y;
    const int p = blockIdx.x * 256 + threadIdx.x;
    const int* __restrict__ segb = seg + b * L_;

    const int cur  = segb[p];
    const int prev = (p == 0) ? -1 : segb[p - 1];

    int* __restrict__ bb = bnd_g + b * (L_ + 1);
    for (int v = prev + 1; v <= cur; v++) bb[v] = p;
    if (p == L_ - 1)
        for (int v = cur + 1; v <= L_; v++) bb[v] = L_;
}

__device__ __forceinline__ uint32_t smem_u32(const void* p) {
    uint32_t a;
    asm("{ .reg .u64 tmp; cvta.to.shared.u64 tmp, %1; cvt.u32.u64 %0, tmp; }"
        : "=r"(a) : "l"(p));
    return a;
}
__device__ __forceinline__ void mbar_init(uint32_t mbar, uint32_t cnt) {
    asm volatile("mbarrier.init.shared.b64 [%0], %1;" :: "r"(mbar), "r"(cnt) : "memory");
}
__device__ __forceinline__ void mbar_expect_tx(uint32_t mbar, uint32_t bytes) {
    asm volatile("mbarrier.arrive.expect_tx.shared.b64 _, [%0], %1;"
                 :: "r"(mbar), "r"(bytes) : "memory");
}
__device__ __forceinline__ void mbar_arrive(uint32_t mbar) {
    asm volatile("mbarrier.arrive.shared.b64 _, [%0];" :: "r"(mbar) : "memory");
}
__device__ __forceinline__ void mbar_wait(uint32_t mbar, uint32_t parity) {
    uint32_t done;
    asm volatile(
        "{\n\t.reg .pred p;\n\t"
        "mbarrier.try_wait.parity.acquire.cta.shared::cta.b64 p, [%1], %2;\n\t"
        "selp.b32 %0, 1, 0, p;\n\t}"
        : "=r"(done) : "r"(mbar), "r"(parity) : "memory");
    if (!done) {
        asm volatile(
            "{\n\t.reg .pred P1;\n\t"
            "WL_%=:\n\t"
            "mbarrier.try_wait.parity.acquire.cta.shared::cta.b64 P1, [%0], %1, 0x989680;\n\t"
            "@P1 bra.uni WD_%=;\n\t"
            "bra.uni WL_%=;\n\t"
            "WD_%=:\n\t}"
            :: "r"(mbar), "r"(parity) : "memory");
    }
}
__device__ __forceinline__ void bulk_copy_g2s(uint32_t dst_smem, const void* src,
                                              uint32_t bytes, uint32_t mbar) {
    asm volatile(
        "cp.async.bulk.shared::cta.global.mbarrier::complete_tx::bytes "
        "[%0], [%1], %2, [%3];"
        :: "r"(dst_smem), "l"(src), "r"(bytes), "r"(mbar) : "memory");
}

__global__ __launch_bounds__(NTHREADS)
void token_segment_sum_kernel(const float* __restrict__ x,
                              float*       __restrict__ out)
{
    __shared__ alignas(16) float4 buf[NSTAGES][SROWS * H4];   // 36 KB
    __shared__ alignas(8) uint64_t mb_full[NSTAGES];
    __shared__ alignas(8) uint64_t mb_empty[NSTAGES];
    __shared__ int bndt[MAX_TILES_PER_CTA][TOK_PER_BLK + 1];  // all my tiles' bounds

    const int bid = blockIdx.x;
    const int t   = threadIdx.x;        // 0..223
    const int wid = t >> 5;             // 0..6 (warp 6 = producer)
    const int lane = t & 31;

    // number of tiles this block owns (strided assignment: bid + k*GRID)
    const int nt = (NUM_TILES - bid + GRID_BLOCKS - 1) / GRID_BLOCKS;

    if (t < NSTAGES) {
        mbar_init(smem_u32(&mb_full[t]), 1);         // completed by TMA tx bytes
        mbar_init(smem_u32(&mb_empty[t]), NCWARPS);  // one arrive per consumer warp
    }

    // load ALL tile bounds for this block in one coalesced sweep
    for (int idx = t; idx < nt * (TOK_PER_BLK + 1); idx += NTHREADS) {
        const int k = idx / (TOK_PER_BLK + 1);
        const int i = idx % (TOK_PER_BLK + 1);
        const int tileIdx = bid + k * GRID_BLOCKS;
        const int b  = tileIdx / TILES_PER_BATCH;
        const int j0 = (tileIdx % TILES_PER_BATCH) * TOK_PER_BLK;
        bndt[k][i] = __ldg(&bnd_g[b * (L_ + 1) + j0 + i]);
    }
    __syncthreads();

    if (wid == NCWARPS) {
        // -------- PRODUCER WARP: stream chunks continuously across tiles ----
        if (lane == 0) {
            int cc = 0;   // global chunk counter (stage = cc%3, usage = cc/3)
            #pragma unroll 1
            for (int k = 0; k < nt; k++) {
                const int tileIdx = bid + k * GRID_BLOCKS;
                const int b = tileIdx / TILES_PER_BATCH;
                const float4* __restrict__ xb =
                    reinterpret_cast<const float4*>(x + (size_t)b * L_ * H_);
                const int s0 = bndt[k][0];
                const int s1 = bndt[k][TOK_PER_BLK];
                #pragma unroll 1
                for (int rbase = s0; rbase < s1; rbase += SROWS) {
                    const int s = cc % NSTAGES;
                    const int u = cc / NSTAGES;
                    if (u > 0)
                        mbar_wait(smem_u32(&mb_empty[s]), (uint32_t)((u - 1) & 1));
                    const uint32_t bytes =
                        (uint32_t)min(SROWS, s1 - rbase) * (H_ * 4);
                    const uint32_t fm = smem_u32(&mb_full[s]);
                    mbar_expect_tx(fm, bytes);
                    bulk_copy_g2s(smem_u32(&buf[s][0]),
                                  &xb[(size_t)rbase * H4], bytes, fm);
                    cc++;
                }
            }
        }
        return;
    }

    // -------- CONSUMER WARPS (192 lanes) --------------------------------
    int cc = 0;   // must mirror producer's chunk sequence exactly
    #pragma unroll 1
    for (int k = 0; k < nt; k++) {
        const int tileIdx = bid + k * GRID_BLOCKS;
        const int b  = tileIdx / TILES_PER_BATCH;
        const int j0 = (tileIdx % TILES_PER_BATCH) * TOK_PER_BLK;
        float4* __restrict__ ob =
            reinterpret_cast<float4*>(out + (size_t)b * L_ * H_);

        const int s0 = bndt[k][0];
        const int s1 = bndt[k][TOK_PER_BLK];

        int j = 0;
        // tokens empty at the very start (bnd[j+1] == s0) -> zero rows
        #pragma unroll 1
        while (j < TOK_PER_BLK && bndt[k][j + 1] == s0) {
            ob[(size_t)(j0 + j) * H4 + t] = make_float4(0.f, 0.f, 0.f, 0.f);
            j++;
        }

        int nb = (j < TOK_PER_BLK) ? bndt[k][j + 1] : -1;
        float4 acc = make_float4(0.f, 0.f, 0.f, 0.f);

        #pragma unroll 1
        for (int rbase = s0; rbase < s1; rbase += SROWS) {
            const int s = cc % NSTAGES;
            const uint32_t ph = (uint32_t)((cc / NSTAGES) & 1);
            const int n = min(SROWS, s1 - rbase);

            mbar_wait(smem_u32(&mb_full[s]), ph);

            #pragma unroll
            for (int i = 0; i < SROWS; i++) {
                if (i < n) {
                    float4 v = buf[s][i * H4 + t];
                    acc.x += v.x; acc.y += v.y;
                    acc.z += v.z; acc.w += v.w;
                    const int pos1 = rbase + i + 1;
                    if (pos1 == nb) {          // token(s) end here
                        do {
                            ob[(size_t)(j0 + j) * H4 + t] = acc;
                            acc = make_float4(0.f, 0.f, 0.f, 0.f);
                            j++;
                            nb = (j < TOK_PER_BLK) ? bndt[k][j + 1] : -1;
                        } while (nb == pos1);  // equal bounds = empty tokens
                    }
                }
            }

            // release the stage — ONE arrive per consumer warp
            __syncwarp();
            if (lane == 0) mbar_arrive(smem_u32(&mb_empty[s]));
            cc++;
        }
    }
}

extern "C" void kernel_launch(void* const* d_in, const int* in_sizes, int n_in,
                              void* d_out, int out_size)
{
    const float* x   = (const float*)d_in[0];   // sequence_output  [B, L, H] f32
    const int*   seg = (const int*)  d_in[1];   // wordpiece_to_token [B, L] i32
    float*       out = (float*)d_out;           // [B, L, H] f32

    dim3 bgrid(L_ / 256, B_);                   // 16 x 16 blocks
    bounds_kernel<<<bgrid, 256>>>(seg);

    dim3 grid(GRID_BLOCKS);                     // 888 persistent blocks
    dim3 block(NTHREADS);                       // 224 threads (6+1 warps)
    token_segment_sum_kernel<<<grid, block>>>(x, out);
}